// round 7
// baseline (speedup 1.0000x reference)
#include <cuda_runtime.h>
#include <cuda_bf16.h>
#include <cstdint>

// support: (2,5,1024,128) -> d_in[0]
// query:   (2,4,1024,128) -> d_in[1]
// out:     (2,4,5,1024,1024) fp32
// sim[b,i,j,m,n] = <q_norm[b,i,m,:], s_norm[b,j,n,:]>
//
// bf16 hi/lo split + mma.sync HMMA, fused 3-pass accumulation
// (hi*hi + hi*lo + lo*hi) with hi fragments loaded ONCE per k16 step.
// 4 macro-steps of K32 staging [hi32|lo32] per 128B row, double-buffered
// cp.async, 64KB smem/CTA -> 2 CTAs/SM.

#define NQ_ROWS 8192
#define NS_ROWS 10240
#define KDIM 128
#define KSPLIT 256  // [hi(128) | lo(128)] bf16 per row

__device__ __align__(16) __nv_bfloat16 g_qs[NQ_ROWS * KSPLIT];
__device__ __align__(16) __nv_bfloat16 g_ss[NS_ROWS * KSPLIT];

__device__ __forceinline__ uint32_t smem_u32(const void* p) {
    uint32_t a;
    asm("{ .reg .u64 t; cvta.to.shared.u64 t, %1; cvt.u32.u64 %0, t; }"
        : "=r"(a) : "l"(p));
    return a;
}

__device__ __forceinline__ void ldm_x4(uint32_t* r, uint32_t addr) {
    asm volatile("ldmatrix.sync.aligned.m8n8.x4.shared.b16 {%0,%1,%2,%3}, [%4];"
        : "=r"(r[0]), "=r"(r[1]), "=r"(r[2]), "=r"(r[3]) : "r"(addr));
}

__device__ __forceinline__ void mma16816(float* d, const uint32_t* a,
                                         const uint32_t* b) {
    asm volatile(
        "mma.sync.aligned.m16n8k16.row.col.f32.bf16.bf16.f32 "
        "{%0,%1,%2,%3}, {%4,%5,%6,%7}, {%8,%9}, {%0,%1,%2,%3};"
        : "+f"(d[0]), "+f"(d[1]), "+f"(d[2]), "+f"(d[3])
        : "r"(a[0]), "r"(a[1]), "r"(a[2]), "r"(a[3]), "r"(b[0]), "r"(b[1]));
}

#define CP_ASYNC16(dst, src) \
    asm volatile("cp.async.cg.shared.global [%0], [%1], 16;" \
        :: "r"(dst), "l"(src) : "memory")
#define CP_COMMIT() asm volatile("cp.async.commit_group;" ::: "memory")
#define CP_WAIT(n)  asm volatile("cp.async.wait_group %0;" :: "n"(n) : "memory")

// ---------------------------------------------------------------------------
// Kernel 1: normalize rows, split into bf16 hi/lo. One warp per row.
// ---------------------------------------------------------------------------
__global__ void normalize_split_kernel(const float* __restrict__ s,
                                       const float* __restrict__ q) {
    int warp_id = (blockIdx.x * blockDim.x + threadIdx.x) >> 5;
    int lane    = threadIdx.x & 31;
    if (warp_id >= NQ_ROWS + NS_ROWS) return;

    const float* src;
    __nv_bfloat16* dst;
    if (warp_id < NQ_ROWS) {
        src = q + (size_t)warp_id * KDIM;
        dst = g_qs + (size_t)warp_id * KSPLIT;
    } else {
        int r = warp_id - NQ_ROWS;
        src = s + (size_t)r * KDIM;
        dst = g_ss + (size_t)r * KSPLIT;
    }

    float4 v = reinterpret_cast<const float4*>(src)[lane];
    float ssum = v.x * v.x + v.y * v.y + v.z * v.z + v.w * v.w;
    #pragma unroll
    for (int o = 16; o > 0; o >>= 1)
        ssum += __shfl_xor_sync(0xffffffffu, ssum, o);
    float rn = 1.0f / fmaxf(sqrtf(ssum), 1e-12f);

    float f[4] = {v.x * rn, v.y * rn, v.z * rn, v.w * rn};
    __nv_bfloat162 hi2[2], lo2[2];
    #pragma unroll
    for (int i = 0; i < 2; i++) {
        __nv_bfloat16 h0 = __float2bfloat16_rn(f[2 * i]);
        __nv_bfloat16 h1 = __float2bfloat16_rn(f[2 * i + 1]);
        __nv_bfloat16 l0 = __float2bfloat16_rn(f[2 * i]     - __bfloat162float(h0));
        __nv_bfloat16 l1 = __float2bfloat16_rn(f[2 * i + 1] - __bfloat162float(h1));
        hi2[i] = __nv_bfloat162(h0, h1);
        lo2[i] = __nv_bfloat162(l0, l1);
    }
    *reinterpret_cast<uint2*>(dst + lane * 4)       = *reinterpret_cast<uint2*>(hi2);
    *reinterpret_cast<uint2*>(dst + 128 + lane * 4) = *reinterpret_cast<uint2*>(lo2);
}

// ---------------------------------------------------------------------------
// Kernel 2: fused-pass pipelined HMMA GEMM. CTA tile 128x128, 8 warps
// (warp 64x32). 4 macro-steps of K32. Buffer row = [hi 32 bf16 | lo 32 bf16]
// = 128B with 16B-chunk XOR swizzle (ch ^ (row&7)) -> conflict-free.
// ---------------------------------------------------------------------------
#define CHUNK_A 16384
#define CHUNK_B 16384
#define BUF_BYTES (CHUNK_A + CHUNK_B)   // 32KB per stage
#define SMEM_BYTES (2 * BUF_BYTES)      // 64KB

__global__ __launch_bounds__(256, 2)
void cosine_hmma_kernel(float* __restrict__ out) {
    extern __shared__ __align__(1024) char smem[];

    int tid  = threadIdx.x;
    int wid  = tid >> 5;
    int lane = tid & 31;

    int p  = blockIdx.z;          // (b*4+i)*5 + j
    int b  = p / 20;
    int ij = p % 20;
    int i  = ij / 5;
    int j  = ij % 5;
    int m0 = blockIdx.y * 128;
    int n0 = blockIdx.x * 128;

    const __nv_bfloat16* abase = g_qs + (size_t)((b * 4 + i) * 1024 + m0) * KSPLIT;
    const __nv_bfloat16* bbase = g_ss + (size_t)((b * 5 + j) * 1024 + n0) * KSPLIT;

    uint32_t smem0 = smem_u32(smem);

    // Stage macro step s into buffer (s&1): per row 8 chunks of 16B:
    // ch 0..3 = hi cols [s*32, s*32+32); ch 4..7 = lo cols [128+s*32, ...).
    auto load_step = [&](int s) {
        uint32_t bufA = smem0 + (uint32_t)(s & 1) * BUF_BYTES;
        uint32_t bufB = bufA + CHUNK_A;
        #pragma unroll
        for (int it = 0; it < 4; it++) {
            int lin = tid + it * 256;    // 0..1023
            int row = lin >> 3;          // 0..127
            int ch  = lin & 7;           // 0..7
            int col = (ch < 4) ? (s * 32 + ch * 8) : (128 + s * 32 + (ch - 4) * 8);
            uint32_t doff = (uint32_t)row * 128u + (uint32_t)((ch ^ (row & 7)) << 4);
            CP_ASYNC16(bufA + doff, abase + (size_t)row * KSPLIT + col);
            CP_ASYNC16(bufB + doff, bbase + (size_t)row * KSPLIT + col);
        }
        CP_COMMIT();
    };

    // ---- warp tiling: 2 warps over m (64), 4 over n (32) ----
    int wm = wid & 1;
    int wn = wid >> 1;
    int mbase = wm * 64;
    int nbase = wn * 32;

    int a_mi   = lane >> 3;
    int a_row0 = mbase + (a_mi & 1) * 8 + (lane & 7);         // + mt*16
    int a_koff = (a_mi >> 1) * 8;                              // 0 or 8
    int b_row0 = nbase + ((lane >> 4) & 1) * 8 + (lane & 7);   // + nt2*16
    int b_koff = ((lane >> 3) & 1) * 8;

    float acc[4][4][4];
    #pragma unroll
    for (int mt = 0; mt < 4; mt++)
        #pragma unroll
        for (int nt = 0; nt < 4; nt++)
            #pragma unroll
            for (int e = 0; e < 4; e++)
                acc[mt][nt][e] = 0.0f;

    load_step(0);

    #pragma unroll
    for (int s = 0; s < 4; s++) {
        if (s + 1 < 4) {
            load_step(s + 1);
            CP_WAIT(1);
        } else {
            CP_WAIT(0);
        }
        __syncthreads();

        uint32_t bufA = smem0 + (uint32_t)(s & 1) * BUF_BYTES;
        uint32_t bufB = bufA + CHUNK_A;

        #pragma unroll
        for (int ks = 0; ks < 2; ks++) {
            int ka = ks * 16 + a_koff;       // 0..31 within hi region
            int kb = ks * 16 + b_koff;
            int achi = ka >> 3;              // hi chunk 0..3
            int bchi = kb >> 3;

            uint32_t aHi[4][4], aLo[4][4];
            #pragma unroll
            for (int mt = 0; mt < 4; mt++) {
                int row = a_row0 + mt * 16;
                uint32_t rb = bufA + (uint32_t)row * 128u;
                ldm_x4(aHi[mt], rb + (uint32_t)(((achi)     ^ (row & 7)) << 4));
                ldm_x4(aLo[mt], rb + (uint32_t)(((achi + 4) ^ (row & 7)) << 4));
            }
            uint32_t bHi[2][4], bLo[2][4];
            #pragma unroll
            for (int nt2 = 0; nt2 < 2; nt2++) {
                int row = b_row0 + nt2 * 16;
                uint32_t rb = bufB + (uint32_t)row * 128u;
                ldm_x4(bHi[nt2], rb + (uint32_t)(((bchi)     ^ (row & 7)) << 4));
                ldm_x4(bLo[nt2], rb + (uint32_t)(((bchi + 4) ^ (row & 7)) << 4));
            }

            #pragma unroll
            for (int mt = 0; mt < 4; mt++) {
                #pragma unroll
                for (int nt = 0; nt < 4; nt++) {
                    const uint32_t* bh = &bHi[nt >> 1][(nt & 1) * 2];
                    const uint32_t* bl = &bLo[nt >> 1][(nt & 1) * 2];
                    mma16816(acc[mt][nt], aHi[mt], bh);   // hi*hi
                    mma16816(acc[mt][nt], aHi[mt], bl);   // hi*lo
                    mma16816(acc[mt][nt], aLo[mt], bh);   // lo*hi
                }
            }
        }
        __syncthreads();
    }

    // ---- Epilogue: direct fragment stores (32B contiguous per quad) ----
    int tr  = lane >> 2;
    int tc2 = (lane & 3) * 2;
    size_t obase = ((size_t)p << 20)
                 + (size_t)(m0 + mbase) * 1024 + (n0 + nbase);
    #pragma unroll
    for (int mt = 0; mt < 4; mt++) {
        #pragma unroll
        for (int nt = 0; nt < 4; nt++) {
            float* r0 = out + obase + (size_t)(mt * 16 + tr) * 1024 + nt * 8 + tc2;
            *reinterpret_cast<float2*>(r0) =
                make_float2(acc[mt][nt][0], acc[mt][nt][1]);
            *reinterpret_cast<float2*>(r0 + 8 * 1024) =
                make_float2(acc[mt][nt][2], acc[mt][nt][3]);
        }
    }
}

extern "C" void kernel_launch(void* const* d_in, const int* in_sizes, int n_in,
                              void* d_out, int out_size) {
    const float* support = (const float*)d_in[0];
    const float* query   = (const float*)d_in[1];
    float* out = (float*)d_out;

    cudaFuncSetAttribute(cosine_hmma_kernel,
                         cudaFuncAttributeMaxDynamicSharedMemorySize, SMEM_BYTES);

    int total_rows = NQ_ROWS + NS_ROWS;
    int blocks1 = (total_rows + 7) / 8;
    normalize_split_kernel<<<blocks1, 256>>>(support, query);

    dim3 grid(8, 8, 40);
    cosine_hmma_kernel<<<grid, 256, SMEM_BYTES>>>(out);
}

// round 8
// speedup vs baseline: 1.3158x; 1.3158x over previous
#include <cuda_runtime.h>
#include <cuda_fp16.h>
#include <cstdint>

// support: (2,5,1024,128) -> d_in[0]
// query:   (2,4,1024,128) -> d_in[1]
// out:     (2,4,5,1024,1024) fp32
// sim[b,i,j,m,n] = <q_norm[b,i,m,:], s_norm[b,j,n,:]>
//
// fp16 2-pass error compensation: A (query) split into fp16 hi+lo,
// B (support) rounded to fp16. D = Ah*Bh + Al*Bh. All values scaled by 32
// (so Al stays in fp16 normal range); epilogue divides by 1024.
// mma.sync HMMA, 4 macro-steps of K64, double-buffered cp.async,
// 64KB smem/CTA -> 2 CTAs/SM.

#define NQ_ROWS 8192
#define NS_ROWS 10240
#define KDIM 128
#define KSPLIT 256   // A rows: [hi(128) | lo(128)] fp16
#define SCALE 32.0f
#define INV_SCALE2 (1.0f / 1024.0f)

__device__ __align__(16) __half g_qs[NQ_ROWS * KSPLIT];
__device__ __align__(16) __half g_ss[NS_ROWS * KDIM];   // hi only

__device__ __forceinline__ uint32_t smem_u32(const void* p) {
    uint32_t a;
    asm("{ .reg .u64 t; cvta.to.shared.u64 t, %1; cvt.u32.u64 %0, t; }"
        : "=r"(a) : "l"(p));
    return a;
}

__device__ __forceinline__ void ldm_x4(uint32_t* r, uint32_t addr) {
    asm volatile("ldmatrix.sync.aligned.m8n8.x4.shared.b16 {%0,%1,%2,%3}, [%4];"
        : "=r"(r[0]), "=r"(r[1]), "=r"(r[2]), "=r"(r[3]) : "r"(addr));
}

__device__ __forceinline__ void mma16816(float* d, const uint32_t* a,
                                         const uint32_t* b) {
    asm volatile(
        "mma.sync.aligned.m16n8k16.row.col.f32.f16.f16.f32 "
        "{%0,%1,%2,%3}, {%4,%5,%6,%7}, {%8,%9}, {%0,%1,%2,%3};"
        : "+f"(d[0]), "+f"(d[1]), "+f"(d[2]), "+f"(d[3])
        : "r"(a[0]), "r"(a[1]), "r"(a[2]), "r"(a[3]), "r"(b[0]), "r"(b[1]));
}

#define CP_ASYNC16(dst, src) \
    asm volatile("cp.async.cg.shared.global [%0], [%1], 16;" \
        :: "r"(dst), "l"(src) : "memory")
#define CP_COMMIT() asm volatile("cp.async.commit_group;" ::: "memory")
#define CP_WAIT(n)  asm volatile("cp.async.wait_group %0;" :: "n"(n) : "memory")

// ---------------------------------------------------------------------------
// Kernel 1: normalize rows; query -> fp16 hi/lo (scaled), support -> fp16 hi.
// One warp per row.
// ---------------------------------------------------------------------------
__global__ void normalize_split_kernel(const float* __restrict__ s,
                                       const float* __restrict__ q) {
    int warp_id = (blockIdx.x * blockDim.x + threadIdx.x) >> 5;
    int lane    = threadIdx.x & 31;
    if (warp_id >= NQ_ROWS + NS_ROWS) return;

    bool is_q = warp_id < NQ_ROWS;
    const float* src = is_q ? q + (size_t)warp_id * KDIM
                            : s + (size_t)(warp_id - NQ_ROWS) * KDIM;

    float4 v = reinterpret_cast<const float4*>(src)[lane];
    float ssum = v.x * v.x + v.y * v.y + v.z * v.z + v.w * v.w;
    #pragma unroll
    for (int o = 16; o > 0; o >>= 1)
        ssum += __shfl_xor_sync(0xffffffffu, ssum, o);
    float rn = SCALE / fmaxf(sqrtf(ssum), 1e-12f);

    float f[4] = {v.x * rn, v.y * rn, v.z * rn, v.w * rn};
    __half h[4];
    #pragma unroll
    for (int e = 0; e < 4; e++) h[e] = __float2half_rn(f[e]);

    if (is_q) {
        __half* dst = g_qs + (size_t)warp_id * KSPLIT;
        __half l[4];
        #pragma unroll
        for (int e = 0; e < 4; e++)
            l[e] = __float2half_rn(f[e] - __half2float(h[e]));
        *reinterpret_cast<uint2*>(dst + lane * 4)       = *reinterpret_cast<uint2*>(h);
        *reinterpret_cast<uint2*>(dst + 128 + lane * 4) = *reinterpret_cast<uint2*>(l);
    } else {
        __half* dst = g_ss + (size_t)(warp_id - NQ_ROWS) * KDIM;
        *reinterpret_cast<uint2*>(dst + lane * 4) = *reinterpret_cast<uint2*>(h);
    }
}

// ---------------------------------------------------------------------------
// Kernel 2: pipelined HMMA GEMM. CTA tile 128x128, 8 warps (warp 64x32).
// 4 macro-steps of K64: (Ah_c0,B_c0), (Ah_c1,B_c1), (Al_c0,B_c0), (Al_c1,B_c1).
// Chunk buffers: A 16KB + B 16KB, double buffered (64KB).
// Rows 64 fp16 = 128B with 16B-chunk XOR swizzle (ch ^ (row&7)).
// ---------------------------------------------------------------------------
#define CHUNK_A 16384
#define CHUNK_B 16384
#define BUF_BYTES (CHUNK_A + CHUNK_B)
#define SMEM_BYTES (2 * BUF_BYTES)

__global__ __launch_bounds__(256, 2)
void cosine_hmma_kernel(float* __restrict__ out) {
    extern __shared__ __align__(1024) char smem[];

    int tid  = threadIdx.x;
    int wid  = tid >> 5;
    int lane = tid & 31;

    int p  = blockIdx.z;          // (b*4+i)*5 + j
    int b  = p / 20;
    int ij = p % 20;
    int i  = ij / 5;
    int j  = ij % 5;
    int m0 = blockIdx.y * 128;
    int n0 = blockIdx.x * 128;

    const __half* abase = g_qs + (size_t)((b * 4 + i) * 1024 + m0) * KSPLIT;
    const __half* bbase = g_ss + (size_t)((b * 5 + j) * 1024 + n0) * KDIM;

    // A source col per macro step: hi c0, hi c1, lo c0, lo c1.
    const int ACOL[4] = {0, 64, 128, 192};
    const int BCOL[4] = {0, 64, 0, 64};

    uint32_t smem0 = smem_u32(smem);

    auto load_step = [&](int s) {
        uint32_t bufA = smem0 + (uint32_t)(s & 1) * BUF_BYTES;
        uint32_t bufB = bufA + CHUNK_A;
        int ac = ACOL[s], bc = BCOL[s];
        #pragma unroll
        for (int it = 0; it < 4; it++) {
            int lin = tid + it * 256;    // 0..1023
            int row = lin >> 3;          // 0..127
            int ch  = lin & 7;           // 0..7 (16B chunks of 128B row)
            uint32_t doff = (uint32_t)row * 128u + (uint32_t)((ch ^ (row & 7)) << 4);
            CP_ASYNC16(bufA + doff, abase + (size_t)row * KSPLIT + ac + ch * 8);
            CP_ASYNC16(bufB + doff, bbase + (size_t)row * KDIM + bc + ch * 8);
        }
        CP_COMMIT();
    };

    // ---- warp tiling: 2 warps over m (64), 4 over n (32) ----
    int wm = wid & 1;
    int wn = wid >> 1;
    int mbase = wm * 64;
    int nbase = wn * 32;

    int a_mi   = lane >> 3;
    int a_row0 = mbase + (a_mi & 1) * 8 + (lane & 7);         // + mt*16
    int a_koff = (a_mi >> 1) * 8;
    int b_row0 = nbase + ((lane >> 4) & 1) * 8 + (lane & 7);  // + nt2*16
    int b_koff = ((lane >> 3) & 1) * 8;

    float acc[4][4][4];
    #pragma unroll
    for (int mt = 0; mt < 4; mt++)
        #pragma unroll
        for (int nt = 0; nt < 4; nt++)
            #pragma unroll
            for (int e = 0; e < 4; e++)
                acc[mt][nt][e] = 0.0f;

    load_step(0);

    #pragma unroll
    for (int s = 0; s < 4; s++) {
        if (s + 1 < 4) {
            load_step(s + 1);
            CP_WAIT(1);
        } else {
            CP_WAIT(0);
        }
        __syncthreads();

        uint32_t bufA = smem0 + (uint32_t)(s & 1) * BUF_BYTES;
        uint32_t bufB = bufA + CHUNK_A;

        #pragma unroll
        for (int ks = 0; ks < 4; ks++) {
            int ka = ks * 16 + a_koff;
            int kb = ks * 16 + b_koff;

            uint32_t aF[4][4];
            #pragma unroll
            for (int mt = 0; mt < 4; mt++) {
                int row = a_row0 + mt * 16;
                uint32_t addr = bufA + (uint32_t)row * 128u
                              + (uint32_t)((((ka >> 3) ^ (row & 7)) << 4));
                ldm_x4(aF[mt], addr);
            }
            uint32_t bF[2][4];
            #pragma unroll
            for (int nt2 = 0; nt2 < 2; nt2++) {
                int row = b_row0 + nt2 * 16;
                uint32_t addr = bufB + (uint32_t)row * 128u
                              + (uint32_t)((((kb >> 3) ^ (row & 7)) << 4));
                ldm_x4(bF[nt2], addr);
            }

            #pragma unroll
            for (int mt = 0; mt < 4; mt++)
                #pragma unroll
                for (int nt = 0; nt < 4; nt++)
                    mma16816(acc[mt][nt], aF[mt], &bF[nt >> 1][(nt & 1) * 2]);
        }
        __syncthreads();
    }

    // ---- Epilogue: scale by 1/1024, direct fragment stores ----
    int tr  = lane >> 2;
    int tc2 = (lane & 3) * 2;
    size_t obase = ((size_t)p << 20)
                 + (size_t)(m0 + mbase) * 1024 + (n0 + nbase);
    #pragma unroll
    for (int mt = 0; mt < 4; mt++) {
        #pragma unroll
        for (int nt = 0; nt < 4; nt++) {
            float* r0 = out + obase + (size_t)(mt * 16 + tr) * 1024 + nt * 8 + tc2;
            *reinterpret_cast<float2*>(r0) =
                make_float2(acc[mt][nt][0] * INV_SCALE2, acc[mt][nt][1] * INV_SCALE2);
            *reinterpret_cast<float2*>(r0 + 8 * 1024) =
                make_float2(acc[mt][nt][2] * INV_SCALE2, acc[mt][nt][3] * INV_SCALE2);
        }
    }
}

extern "C" void kernel_launch(void* const* d_in, const int* in_sizes, int n_in,
                              void* d_out, int out_size) {
    const float* support = (const float*)d_in[0];
    const float* query   = (const float*)d_in[1];
    float* out = (float*)d_out;

    cudaFuncSetAttribute(cosine_hmma_kernel,
                         cudaFuncAttributeMaxDynamicSharedMemorySize, SMEM_BYTES);

    int total_rows = NQ_ROWS + NS_ROWS;
    int blocks1 = (total_rows + 7) / 8;
    normalize_split_kernel<<<blocks1, 256>>>(support, query);

    dim3 grid(8, 8, 40);
    cosine_hmma_kernel<<<grid, 256, SMEM_BYTES>>>(out);
}